// round 13
// baseline (speedup 1.0000x reference)
#include <cuda_runtime.h>
#include <cstdint>

#define NATOMS 6144
#define FDIM   128
#define HDIM   64
#define NMOL   48
#define NBLK   148     // co-resident on B300(148)/GB300(152)
#define NTHR   768
#define NWARP  24
#define NWTOT  (NBLK * NWARP)
#define ASLOT  42      // exact atom slots (acnt is 41..42)
#define NPAIRS 21

// Device-global scratch. Deterministic overwrites; g_qsumF is zero at load and
// re-zeroed by the last-arriving block each replay (after all reads).
__device__ float4 g_A[NATOMS];        // pos.xyz, q_raw
__device__ float4 g_B[NATOMS];        // mu.xyz, sqrt(softplus(c6))
__device__ int    g_segs[NMOL];
__device__ int    g_sege[NMOL];
__device__ float  g_qsumF[NMOL];      // per-molecule q sums (atomic, replay-safe)
__device__ double g_partial[NBLK];
__device__ volatile int g_sense;
__device__ int    g_count;
__device__ int    g_done;

__device__ __forceinline__ void grid_barrier() {
    __syncthreads();
    if (threadIdx.x == 0) {
        int s = g_sense;
        __threadfence();
        if (atomicAdd(&g_count, 1) == NBLK - 1) {
            g_count = 0;
            __threadfence();
            g_sense = s ^ 1;
        } else {
            while (g_sense == s) { }
        }
    }
    __syncthreads();
    __threadfence();
}

// ---- f32x2 packed-FMA helpers (FFMA2 on sm_100+) ---------------------------
__device__ __forceinline__ long long dupf(float w) {
    long long d; unsigned r = __float_as_uint(w);
    asm("mov.b64 %0, {%1, %1};" : "=l"(d) : "r"(r));
    return d;
}
__device__ __forceinline__ void ffma2(long long& a, long long h, long long w) {
    asm("fma.rn.f32x2 %0, %1, %2, %0;" : "+l"(a) : "l"(h), "l"(w));
}
__device__ __forceinline__ void unpack2(long long a, float& lo, float& hi) {
    unsigned l, h;
    asm("mov.b64 {%0, %1}, %2;" : "=r"(l), "=r"(h) : "l"(a));
    lo = __uint_as_float(l); hi = __uint_as_float(h);
}

__device__ __forceinline__ void tma_bulk_1d(uint32_t dst, const void* src,
                                            uint32_t bytes, uint32_t mbar) {
    asm volatile(
        "cp.async.bulk.shared::cta.global.mbarrier::complete_tx::bytes [%0], [%1], %2, [%3];"
        :: "r"(dst), "l"(src), "r"(bytes), "r"(mbar) : "memory");
}
__device__ __forceinline__ void mbar_wait0(uint32_t mb) {
    asm volatile(
        "{\n\t.reg .pred P;\n"
        "WAIT_%=:\n\t"
        "mbarrier.try_wait.parity.acquire.cta.shared::cta.b64 P, [%0], 0, 0x989680;\n\t"
        "@!P bra WAIT_%=;\n\t}"
        :: "r"(mb) : "memory");
}

extern "C" __global__ void __launch_bounds__(NTHR, 1) fused_kernel(
    const float* __restrict__ h0, const float* __restrict__ h1,
    const float* __restrict__ pos, const int* __restrict__ batch,
    const float* __restrict__ qW1, const float* __restrict__ qb1,
    const float* __restrict__ qW2, const float* __restrict__ qb2,
    const float* __restrict__ cW1, const float* __restrict__ cb1,
    const float* __restrict__ cW2, const float* __restrict__ cb2,
    const float* __restrict__ muW, float* __restrict__ out)
{
    extern __shared__ float smem[];
    float* sH0P = smem;                         // 21 pairs x 256 floats = 21 KB
    float* sWq  = smem + NPAIRS * 256;          // 32 KB (TMA dst)
    float* sWc  = sWq + FDIM * HDIM;            // 32 KB (TMA dst)
    long long* sComb = (long long*)(sWc + FDIM * HDIM);   // 6*32*14 ll = 21 KB

    __shared__ float  sPQ[3][14];
    __shared__ float  sPC[3][14];
    __shared__ float  s_mu[ASLOT][3];
    __shared__ float  s_qp[NMOL];
    __shared__ float  s_qmean[NMOL];
    __shared__ double sDD[NWARP];
    __shared__ int    s_last;
    __shared__ __align__(8) unsigned long long mbar[1];

    const int tid  = threadIdx.x;
    const int bid  = blockIdx.x;
    const int w    = tid >> 5;
    const int lane = tid & 31;

    const int astart = (bid * NATOMS) / NBLK;
    const int aend   = ((bid + 1) * NATOMS) / NBLK;
    const int acnt   = aend - astart;          // 41 or 42

    const uint32_t mb   = (uint32_t)__cvta_generic_to_shared(mbar);
    const uint32_t sWqu = (uint32_t)__cvta_generic_to_shared(sWq);
    const uint32_t sWcu = (uint32_t)__cvta_generic_to_shared(sWc);

    if (tid == 0)
        asm volatile("mbarrier.init.shared.b64 [%0], 1;" :: "r"(mb) : "memory");
    if (tid < NMOL) s_qp[tid] = 0.0f;
    __syncthreads();

    // ========== Warp-specialized phase 1 ====================================
    if (w < 12) {
        // ---- weights via TMA (kick first; h0 staging overlaps the flight) --
        if (tid == 0) {
            asm volatile("mbarrier.arrive.expect_tx.shared.b64 _, [%0], %1;"
                         :: "r"(mb), "r"(2u * FDIM * HDIM * 4u) : "memory");
            tma_bulk_1d(sWqu, qW1, FDIM * HDIM * 4u, mb);
            tma_bulk_1d(sWcu, cW1, FDIM * HDIM * 4u, mb);
        }

        // ---- h0: coalesced LDG.128 -> transformed STS (single pass) --------
        // word index for (atom a, feature f): (a>>1)*256 + f*2 + (a&1)
        {
            const float4 z4 = make_float4(0.f, 0.f, 0.f, 0.f);
            float4 v[4]; int av[4], fv[4]; bool ok[4];
            #pragma unroll
            for (int s = 0; s < 4; s++) {
                const int idx = tid + s * 384;
                av[s] = idx >> 5; fv[s] = (idx & 31) * 4;
                ok[s] = (idx < ASLOT * 32);
                v[s]  = (ok[s] && av[s] < acnt)
                    ? *reinterpret_cast<const float4*>(
                          h0 + (size_t)(astart + av[s]) * FDIM + fv[s])
                    : z4;
            }
            #pragma unroll
            for (int s = 0; s < 4; s++) {
                if (ok[s]) {
                    const int base = (av[s] >> 1) * 256 + (av[s] & 1);
                    sH0P[base + (fv[s] + 0) * 2] = v[s].x;
                    sH0P[base + (fv[s] + 1) * 2] = v[s].y;
                    sH0P[base + (fv[s] + 2) * 2] = v[s].z;
                    sH0P[base + (fv[s] + 3) * 2] = v[s].w;
                }
            }
        }
        asm volatile("bar.sync 1, 384;" ::: "memory");
        mbar_wait0(mb);                        // weights landed (TMA flew during staging)

        // ---- MLPs: 12 warps = 2 MLPs x 3 pair-groups x 2 f-halves ----------
        // Each lane owns units {2*lane, 2*lane+1}; 7 atom-pairs per warp.
        const int sec = w / 6;                 // 0 = q, 1 = c6
        const int wl  = w % 6;
        const int pg  = wl >> 1;               // pair-group (7 pairs = 14 atoms)
        const int fh  = wl & 1;                // feature half
        const float* sW = sec ? sWc : sWq;
        const float* B1 = sec ? cb1 : qb1;
        const float* W2 = sec ? cW2 : qW2;

        long long acc[7][2];
        #pragma unroll
        for (int p = 0; p < 7; p++) { acc[p][0] = 0; acc[p][1] = 0; }
        const int pb = pg * 7;

        #pragma unroll 2
        for (int f4 = fh * 16; f4 < fh * 16 + 16; f4++) {
            float2 wv[4];
            #pragma unroll
            for (int k = 0; k < 4; k++)
                wv[k] = *reinterpret_cast<const float2*>(
                    &sW[(4 * f4 + k) * HDIM + 2 * lane]);
            const long long u0w0 = dupf(wv[0].x), u1w0 = dupf(wv[0].y);
            const long long u0w1 = dupf(wv[1].x), u1w1 = dupf(wv[1].y);
            const long long u0w2 = dupf(wv[2].x), u1w2 = dupf(wv[2].y);
            const long long u0w3 = dupf(wv[3].x), u1w3 = dupf(wv[3].y);
            #pragma unroll
            for (int p = 0; p < 7; p++) {
                const double2* hp = reinterpret_cast<const double2*>(
                    &sH0P[(pb + p) * 256 + f4 * 8]);
                const double2 hA = hp[0];      // feats 4f4, 4f4+1 (atom-pair packed)
                const double2 hB = hp[1];      // feats 4f4+2, 4f4+3
                const long long a0 = __double_as_longlong(hA.x);
                const long long a1 = __double_as_longlong(hA.y);
                const long long a2 = __double_as_longlong(hB.x);
                const long long a3 = __double_as_longlong(hB.y);
                ffma2(acc[p][0], a0, u0w0); ffma2(acc[p][1], a0, u1w0);
                ffma2(acc[p][0], a1, u0w1); ffma2(acc[p][1], a1, u1w1);
                ffma2(acc[p][0], a2, u0w2); ffma2(acc[p][1], a2, u1w2);
                ffma2(acc[p][0], a3, u0w3); ffma2(acc[p][1], a3, u1w3);
            }
        }

        // ---- combine f-halves through smem ---------------------------------
        const int slot = ((sec * 3 + pg) * 32 + lane) * 14;
        if (fh == 0) {
            #pragma unroll
            for (int p = 0; p < 7; p++) {
                sComb[slot + 2 * p]     = acc[p][0];
                sComb[slot + 2 * p + 1] = acc[p][1];
            }
        }
        asm volatile("bar.sync 1, 384;" ::: "memory");
        if (fh == 1) {
            const float2 b1v = *reinterpret_cast<const float2*>(&B1[2 * lane]);
            const float2 w2v = *reinterpret_cast<const float2*>(&W2[2 * lane]);
            float v[14];
            #pragma unroll
            for (int p = 0; p < 7; p++) {
                float hA0, hB0, hA1, hB1, oA0, oB0, oA1, oB1;
                unpack2(acc[p][0], hA0, hB0);
                unpack2(acc[p][1], hA1, hB1);
                unpack2(sComb[slot + 2 * p],     oA0, oB0);
                unpack2(sComb[slot + 2 * p + 1], oA1, oB1);
                const float xA0 = hA0 + oA0 + b1v.x;
                const float xB0 = hB0 + oB0 + b1v.x;
                const float xA1 = hA1 + oA1 + b1v.y;
                const float xB1 = hB1 + oB1 + b1v.y;
                const float sA0 = xA0 * __fdividef(1.0f, 1.0f + __expf(-xA0)) * w2v.x;
                const float sB0 = xB0 * __fdividef(1.0f, 1.0f + __expf(-xB0)) * w2v.x;
                const float sA1 = xA1 * __fdividef(1.0f, 1.0f + __expf(-xA1)) * w2v.y;
                const float sB1 = xB1 * __fdividef(1.0f, 1.0f + __expf(-xB1)) * w2v.y;
                v[2 * p]     = sA0 + sA1;      // atom 2(pb+p)
                v[2 * p + 1] = sB0 + sB1;      // atom 2(pb+p)+1
            }
            #pragma unroll
            for (int k = 0; k < 14; k++) {
                #pragma unroll
                for (int o = 16; o > 0; o >>= 1)
                    v[k] += __shfl_down_sync(0xffffffffu, v[k], o);
            }
            if (lane == 0) {
                float (*dst)[14] = sec ? sPC : sPQ;
                #pragma unroll
                for (int k = 0; k < 14; k++) dst[pg][k] = v[k];
            }
        }
    } else {
        // ---- mu warps (12-23): start immediately, h1 from global -----------
        const float4 mw4 = *reinterpret_cast<const float4*>(muW + lane * 4);
        for (int loc = w - 12; loc < acnt; loc += 12) {
            const float* hr = h1 + (size_t)(astart + loc) * 3 * FDIM;
            float m[3];
            #pragma unroll
            for (int d = 0; d < 3; d++) {
                const float4 a = *reinterpret_cast<const float4*>(hr + d * FDIM + lane * 4);
                m[d] = a.x * mw4.x + a.y * mw4.y + a.z * mw4.z + a.w * mw4.w;
            }
            #pragma unroll
            for (int o = 16; o > 0; o >>= 1) {
                m[0] += __shfl_down_sync(0xffffffffu, m[0], o);
                m[1] += __shfl_down_sync(0xffffffffu, m[1], o);
                m[2] += __shfl_down_sync(0xffffffffu, m[2], o);
            }
            if (lane == 0) { s_mu[loc][0] = m[0]; s_mu[loc][1] = m[1]; s_mu[loc][2] = m[2]; }
        }
    }
    __syncthreads();

    // ---- Pack per-atom data + segment boundaries + molecule q partials -----
    if (tid < acnt) {
        const int grp = tid / 14, idx = tid % 14;
        const float qv  = sPQ[grp][idx] + qb2[0];
        const float cv  = sPC[grp][idx] + cb2[0];
        const float sp  = fmaxf(cv, 0.0f) + log1pf(__expf(-fabsf(cv)));
        const int i = astart + tid;
        const int b = batch[i];
        g_A[i] = make_float4(pos[3 * i], pos[3 * i + 1], pos[3 * i + 2], qv);
        g_B[i] = make_float4(s_mu[tid][0], s_mu[tid][1], s_mu[tid][2], sqrtf(sp));
        if (i == 0 || batch[i - 1] != b) g_segs[b] = i;
        if (i == NATOMS - 1 || batch[i + 1] != b) g_sege[b] = i + 1;
        atomicAdd(&s_qp[b], qv);
    }
    __syncthreads();
    // push nonzero partials (adding 0.0 is a no-op, so the guard is exact)
    if (tid < NMOL && s_qp[tid] != 0.0f) atomicAdd(&g_qsumF[tid], s_qp[tid]);

    grid_barrier();

    // ---- qmean staging: one LDG round (sums already global-complete) -------
    if (tid < NMOL) {
        const int cnt = g_sege[tid] - g_segs[tid];
        s_qmean[tid] = (cnt > 0) ? g_qsumF[tid] / (float)cnt : 0.0f;
    }
    __syncthreads();

    // ---- Pairwise energy (i<j; all terms symmetric), 2-stage pipelined -----
    double acc2 = 0.0;
    for (int i = bid * NWARP + w; i < NATOMS; i += NWTOT) {
        const int b  = batch[i];
        const int e0 = g_sege[b];
        const float qm = s_qmean[b];

        const float4 Ai = g_A[i];
        const float4 Bi = g_B[i];
        const float qi14 = (Ai.w - qm) * 14.399f;

        float facc = 0.0f;
        int j = i + 1 + lane;
        if (j < e0) {
            float4 Aj = g_A[j];
            float4 Bj = g_B[j];
            while (true) {
                const int jn = j + 32;
                float4 An, Bn;
                if (jn < e0) { An = g_A[jn]; Bn = g_B[jn]; }   // prefetch

                const float dx = Ai.x - Aj.x;
                const float dy = Ai.y - Aj.y;
                const float dz = Ai.z - Aj.z;
                const float d2r  = dx * dx + dy * dy + dz * dz;
                const float d2   = d2r + 1e-8f;
                const float invd = rsqrtf(d2);                    // MUFU 1
                const float dist = d2 * invd;

                const float qj    = Aj.w - qm;
                const float taper = 1.0f - __expf(-0.5f * dist);  // MUFU 2
                const float ec    = qi14 * qj * invd * taper;

                const float r6    = d2r * d2r * d2r;
                const float aden  = r6 + 20.0f;
                const float bden  = d2r * dist + 10.0f;
                const float invab = __fdividef(1.0f, aden * bden); // MUFU 3

                const float ev = -Bi.w * Bj.w * (invab * bden);

                const float mumu = Bi.x * Bj.x + Bi.y * Bj.y + Bi.z * Bj.z;
                const float di   = (Bi.x * dx + Bi.y * dy + Bi.z * dz) * invd;
                const float dj   = (Bj.x * dx + Bj.y * dy + Bj.z * dz) * invd;
                const float ed   = (mumu - 3.0f * di * dj) * (invab * aden);

                facc += ec + ev + ed;

                if (jn >= e0) break;
                Aj = An; Bj = Bn; j = jn;
            }
        }
        acc2 += (double)facc;
    }

    #pragma unroll
    for (int o = 16; o > 0; o >>= 1)
        acc2 += __shfl_down_sync(0xffffffffu, acc2, o);
    if (lane == 0) sDD[w] = acc2;
    __syncthreads();
    if (tid == 0) {
        double ts = 0.0;
        #pragma unroll
        for (int k = 0; k < NWARP; k++) ts += sDD[k];
        g_partial[bid] = ts;
        __threadfence();
        s_last = (atomicAdd(&g_done, 1) == NBLK - 1) ? 1 : 0;
    }
    __syncthreads();

    // ---- Last-arriving block: zero qsum for next replay, reduce, write -----
    if (s_last) {
        __threadfence();
        if (tid == 0) g_done = 0;
        if (tid < NMOL) g_qsumF[tid] = 0.0f;   // all readers finished (ticket)
        double v = (tid < NBLK) ? g_partial[tid] : 0.0;
        #pragma unroll
        for (int o = 16; o > 0; o >>= 1)
            v += __shfl_down_sync(0xffffffffu, v, o);
        if (lane == 0 && w < 5) sDD[w] = v;
        __syncthreads();
        if (tid == 0) {
            double tot = 0.0;
            #pragma unroll
            for (int k = 0; k < 5; k++) tot += sDD[k];
            out[0] = (float)tot;               // LONG_RANGE_SCALE = 1.0
        }
    }
}

// ---------------------------------------------------------------------------
extern "C" void kernel_launch(void* const* d_in, const int* in_sizes, int n_in,
                              void* d_out, int out_size) {
    const float* h0    = (const float*)d_in[0];
    const float* h1    = (const float*)d_in[1];
    const float* pos   = (const float*)d_in[2];
    const int*   batch = (const int*)  d_in[3];
    const float* qW1   = (const float*)d_in[4];
    const float* qb1   = (const float*)d_in[5];
    const float* qW2   = (const float*)d_in[6];
    const float* qb2   = (const float*)d_in[7];
    const float* cW1   = (const float*)d_in[8];
    const float* cb1   = (const float*)d_in[9];
    const float* cW2   = (const float*)d_in[10];
    const float* cb2   = (const float*)d_in[11];
    const float* muW   = (const float*)d_in[12];

    // sH0P (21*256 f) + sWq + sWc (2*8192 f) + sComb (6*32*14 ll)
    const int smem_bytes = NPAIRS * 256 * 4 + 2 * FDIM * HDIM * 4
                         + 6 * 32 * 14 * 8;   // ~106 KB
    cudaFuncSetAttribute(fused_kernel,
                         cudaFuncAttributeMaxDynamicSharedMemorySize, smem_bytes);
    fused_kernel<<<NBLK, NTHR, smem_bytes>>>(
        h0, h1, pos, batch,
        qW1, qb1, qW2, qb2,
        cW1, cb1, cW2, cb2,
        muW, (float*)d_out);
}

// round 14
// speedup vs baseline: 1.0555x; 1.0555x over previous
#include <cuda_runtime.h>
#include <cstdint>

#define NATOMS 6144
#define FDIM   128
#define HDIM   64
#define NMOL   48
#define NBLK   148     // co-resident on B300(148)/GB300(152)
#define NTHR   768
#define NWARP  24
#define NWTOT  (NBLK * NWARP)
#define AROW   48      // padded atom rows (3 m-tiles of 16); acnt is 41..42
#define WPAD   68      // row stride in 32-bit words (136 bf16) -> conflict-free frags

// smem word offsets (uint32 units)
#define OFF_WF  0                  // fp32 weights TMA dst: 2*8192 = 16384 words
#define OFF_AH  16384              // A-hi bf16: 48*68 = 3264
#define OFF_AL  (OFF_AH + 3264)
#define OFF_WH  (OFF_AL + 3264)    // W-hi bf16: 128*68 = 8704
#define OFF_WL  (OFF_WH + 8704)
#define SMEM_WORDS (OFF_WL + 8704) // 40320 words = 157.5 KB

// Device-global scratch. Deterministic overwrites; g_qsumF zero at load and
// re-zeroed by the last-arriving block each replay (after all reads).
__device__ float4 g_A[NATOMS];        // pos.xyz, q_raw
__device__ float4 g_B[NATOMS];        // mu.xyz, sqrt(softplus(c6))
__device__ int    g_segs[NMOL];
__device__ int    g_sege[NMOL];
__device__ float  g_qsumF[NMOL];
__device__ double g_partial[NBLK];
__device__ volatile int g_sense;
__device__ int    g_count;
__device__ int    g_done;

__device__ __forceinline__ void grid_barrier() {
    __syncthreads();
    if (threadIdx.x == 0) {
        int s = g_sense;
        __threadfence();
        if (atomicAdd(&g_count, 1) == NBLK - 1) {
            g_count = 0;
            __threadfence();
            g_sense = s ^ 1;
        } else {
            while (g_sense == s) { }
        }
    }
    __syncthreads();
    __threadfence();
}

// pack {low=x, high=y} as bf16x2 (hi) and the bf16x2 of the residuals (lo)
__device__ __forceinline__ uint2 bf16split2(float x, float y) {
    uint32_t h, l;
    asm("cvt.rn.bf16x2.f32 %0, %1, %2;" : "=r"(h) : "f"(y), "f"(x));
    const float rx = x - __uint_as_float(h << 16);
    const float ry = y - __uint_as_float(h & 0xffff0000u);
    asm("cvt.rn.bf16x2.f32 %0, %1, %2;" : "=r"(l) : "f"(ry), "f"(rx));
    return make_uint2(h, l);
}

__device__ __forceinline__ void mma16816(float* d, const uint32_t* a,
                                         uint32_t b0, uint32_t b1) {
    asm volatile(
        "mma.sync.aligned.m16n8k16.row.col.f32.bf16.bf16.f32 "
        "{%0,%1,%2,%3}, {%4,%5,%6,%7}, {%8,%9}, {%0,%1,%2,%3};"
        : "+f"(d[0]), "+f"(d[1]), "+f"(d[2]), "+f"(d[3])
        : "r"(a[0]), "r"(a[1]), "r"(a[2]), "r"(a[3]), "r"(b0), "r"(b1));
}

__device__ __forceinline__ void tma_bulk_1d(uint32_t dst, const void* src,
                                            uint32_t bytes, uint32_t mbar) {
    asm volatile(
        "cp.async.bulk.shared::cta.global.mbarrier::complete_tx::bytes [%0], [%1], %2, [%3];"
        :: "r"(dst), "l"(src), "r"(bytes), "r"(mbar) : "memory");
}
__device__ __forceinline__ void mbar_wait0(uint32_t mb) {
    asm volatile(
        "{\n\t.reg .pred P;\n"
        "WAIT_%=:\n\t"
        "mbarrier.try_wait.parity.acquire.cta.shared::cta.b64 P, [%0], 0, 0x989680;\n\t"
        "@!P bra WAIT_%=;\n\t}"
        :: "r"(mb) : "memory");
}

extern "C" __global__ void __launch_bounds__(NTHR, 1) fused_kernel(
    const float* __restrict__ h0, const float* __restrict__ h1,
    const float* __restrict__ pos, const int* __restrict__ batch,
    const float* __restrict__ qW1, const float* __restrict__ qb1,
    const float* __restrict__ qW2, const float* __restrict__ qb2,
    const float* __restrict__ cW1, const float* __restrict__ cb1,
    const float* __restrict__ cW2, const float* __restrict__ cb2,
    const float* __restrict__ muW, float* __restrict__ out)
{
    extern __shared__ uint32_t sm[];
    float*    sWf = (float*)(sm + OFF_WF);
    uint32_t* sAh = sm + OFF_AH;
    uint32_t* sAl = sm + OFF_AL;
    uint32_t* sWh = sm + OFF_WH;
    uint32_t* sWl = sm + OFF_WL;

    __shared__ float  sQ[AROW], sC[AROW];      // per-atom MLP outputs (atomic acc)
    __shared__ float  s_b1[128], s_w2[128];
    __shared__ float  s_mu[AROW][3];
    __shared__ float  s_qp[NMOL];
    __shared__ float  s_qmean[NMOL];
    __shared__ double sDD[NWARP];
    __shared__ int    s_last;
    __shared__ __align__(8) unsigned long long mbar[1];

    const int tid  = threadIdx.x;
    const int bid  = blockIdx.x;
    const int w    = tid >> 5;
    const int lane = tid & 31;

    const int astart = (bid * NATOMS) / NBLK;
    const int aend   = ((bid + 1) * NATOMS) / NBLK;
    const int acnt   = aend - astart;          // 41 or 42

    const uint32_t mb   = (uint32_t)__cvta_generic_to_shared(mbar);
    const uint32_t sWfu = (uint32_t)__cvta_generic_to_shared(sWf);

    if (tid == 0)
        asm volatile("mbarrier.init.shared.b64 [%0], 1;" :: "r"(mb) : "memory");
    if (tid < NMOL) s_qp[tid] = 0.0f;
    if (tid < AROW) { sQ[tid] = 0.0f; sC[tid] = 0.0f; }
    __syncthreads();

    // ========== Warp-specialized phase 1 ====================================
    if (w < 12) {
        // ---- kick fp32 weight TMA (64 KB) ----------------------------------
        if (tid == 0) {
            asm volatile("mbarrier.arrive.expect_tx.shared.b64 _, [%0], %1;"
                         :: "r"(mb), "r"(2u * FDIM * HDIM * 4u) : "memory");
            tma_bulk_1d(sWfu, qW1, FDIM * HDIM * 4u, mb);
            tma_bulk_1d(sWfu + FDIM * HDIM * 4u, cW1, FDIM * HDIM * 4u, mb);
        }
        // ---- stage b1 / W2 (units 0-63 q, 64-127 c6) -----------------------
        if (tid < 64)       { s_b1[tid] = qb1[tid];      s_w2[tid] = qW2[tid]; }
        else if (tid < 128) { s_b1[tid] = cb1[tid - 64]; s_w2[tid] = cW2[tid - 64]; }

        // ---- acts: LDG.128 -> bf16 hi/lo split -> STS (rows padded to 48) --
        #pragma unroll
        for (int s = 0; s < 4; s++) {
            const int idx = tid + s * 384;     // < 1536 = 48 rows x 32 float4
            const int a  = idx >> 5;
            const int f0 = (idx & 31) * 4;
            float4 v = make_float4(0.f, 0.f, 0.f, 0.f);
            if (a < acnt)
                v = *reinterpret_cast<const float4*>(
                        h0 + (size_t)(astart + a) * FDIM + f0);
            const uint2 p01 = bf16split2(v.x, v.y);
            const uint2 p23 = bf16split2(v.z, v.w);
            const int base = a * WPAD + (f0 >> 1);
            sAh[base]     = p01.x; sAh[base + 1] = p23.x;
            sAl[base]     = p01.y; sAl[base + 1] = p23.y;
        }

        mbar_wait0(mb);                        // fp32 weights landed

        // ---- weights: smem fp32 -> bf16 hi/lo, layout [unit n][k] padded ---
        {
            uint16_t* wh16 = (uint16_t*)sWh;
            uint16_t* wl16 = (uint16_t*)sWl;
            const float2* wf2 = (const float2*)sWf;
            for (int e = tid; e < 8192; e += 384) {
                const int m  = e >> 12;        // 0 = q, 1 = c6
                const int r  = e & 4095;
                const int f  = r >> 5;         // k index
                const int up = r & 31;         // unit pair
                const float2 wv = wf2[m * 4096 + f * 32 + up];
                const uint2 hl = bf16split2(wv.x, wv.y);
                const int n = m * 64 + 2 * up;
                wh16[n * 136 + f]       = (uint16_t)(hl.x & 0xffffu);
                wh16[(n + 1) * 136 + f] = (uint16_t)(hl.x >> 16);
                wl16[n * 136 + f]       = (uint16_t)(hl.y & 0xffffu);
                wl16[(n + 1) * 136 + f] = (uint16_t)(hl.y >> 16);
            }
        }
        asm volatile("bar.sync 1, 384;" ::: "memory");

        // ---- HMMA GEMM: 12 warps = 3 m-tiles x 4 n-quads -------------------
        // D = Ah*Bh + Ah*Bl + Al*Bh  (split-bf16, fp32 accum)
        const int m  = w >> 2;                 // m-tile (rows 16m..16m+15)
        const int nq = w & 3;                  // n-quad (cols nq*32..nq*32+31)
        const int g  = lane >> 2;              // fragment group row/col
        const int t  = lane & 3;

        float D[4][4];
        #pragma unroll
        for (int nb = 0; nb < 4; nb++)
            #pragma unroll
            for (int k = 0; k < 4; k++) D[nb][k] = 0.0f;

        const int ar0 = (16 * m + g) * WPAD;
        const int ar1 = (16 * m + g + 8) * WPAD;

        #pragma unroll
        for (int kk = 0; kk < 8; kk++) {
            const int kw = kk * 8 + t;
            uint32_t ah[4], al[4];
            ah[0] = sAh[ar0 + kw];     ah[1] = sAh[ar1 + kw];
            ah[2] = sAh[ar0 + kw + 4]; ah[3] = sAh[ar1 + kw + 4];
            al[0] = sAl[ar0 + kw];     al[1] = sAl[ar1 + kw];
            al[2] = sAl[ar0 + kw + 4]; al[3] = sAl[ar1 + kw + 4];
            #pragma unroll
            for (int nb = 0; nb < 4; nb++) {
                const int wb = (nq * 32 + nb * 8 + g) * WPAD + kw;
                const uint32_t bh0 = sWh[wb], bh1 = sWh[wb + 4];
                const uint32_t bl0 = sWl[wb], bl1 = sWl[wb + 4];
                mma16816(D[nb], ah, bh0, bh1);
                mma16816(D[nb], ah, bl0, bl1);
                mma16816(D[nb], al, bh0, bh1);
            }
        }

        // ---- epilogue: silu * W2 in fragments, butterfly, shared atomics ---
        float sum0 = 0.0f, sum1 = 0.0f;
        #pragma unroll
        for (int nb = 0; nb < 4; nb++) {
            const int c0 = nq * 32 + nb * 8 + 2 * t;
            const int c1 = c0 + 1;
            const float b0 = s_b1[c0], b1v = s_b1[c1];
            const float w0 = s_w2[c0], w1v = s_w2[c1];
            float x;
            x = D[nb][0] + b0;  sum0 += x * __fdividef(1.0f, 1.0f + __expf(-x)) * w0;
            x = D[nb][1] + b1v; sum0 += x * __fdividef(1.0f, 1.0f + __expf(-x)) * w1v;
            x = D[nb][2] + b0;  sum1 += x * __fdividef(1.0f, 1.0f + __expf(-x)) * w0;
            x = D[nb][3] + b1v; sum1 += x * __fdividef(1.0f, 1.0f + __expf(-x)) * w1v;
        }
        sum0 += __shfl_xor_sync(0xffffffffu, sum0, 1);
        sum0 += __shfl_xor_sync(0xffffffffu, sum0, 2);
        sum1 += __shfl_xor_sync(0xffffffffu, sum1, 1);
        sum1 += __shfl_xor_sync(0xffffffffu, sum1, 2);
        if (t == 0) {
            float* dst = (nq < 2) ? sQ : sC;
            atomicAdd(&dst[16 * m + g],     sum0);
            atomicAdd(&dst[16 * m + g + 8], sum1);
        }
    } else {
        // ---- mu warps (12-23): start immediately, h1 from global -----------
        const float4 mw4 = *reinterpret_cast<const float4*>(muW + lane * 4);
        for (int loc = w - 12; loc < acnt; loc += 12) {
            const float* hr = h1 + (size_t)(astart + loc) * 3 * FDIM;
            float mv[3];
            #pragma unroll
            for (int d = 0; d < 3; d++) {
                const float4 a = *reinterpret_cast<const float4*>(hr + d * FDIM + lane * 4);
                mv[d] = a.x * mw4.x + a.y * mw4.y + a.z * mw4.z + a.w * mw4.w;
            }
            #pragma unroll
            for (int o = 16; o > 0; o >>= 1) {
                mv[0] += __shfl_down_sync(0xffffffffu, mv[0], o);
                mv[1] += __shfl_down_sync(0xffffffffu, mv[1], o);
                mv[2] += __shfl_down_sync(0xffffffffu, mv[2], o);
            }
            if (lane == 0) { s_mu[loc][0] = mv[0]; s_mu[loc][1] = mv[1]; s_mu[loc][2] = mv[2]; }
        }
    }
    __syncthreads();

    // ---- Pack per-atom data + segment boundaries + molecule q partials -----
    if (tid < acnt) {
        const float qv = sQ[tid] + qb2[0];
        const float cv = sC[tid] + cb2[0];
        const float sp = fmaxf(cv, 0.0f) + log1pf(__expf(-fabsf(cv)));
        const int i = astart + tid;
        const int b = batch[i];
        g_A[i] = make_float4(pos[3 * i], pos[3 * i + 1], pos[3 * i + 2], qv);
        g_B[i] = make_float4(s_mu[tid][0], s_mu[tid][1], s_mu[tid][2], sqrtf(sp));
        if (i == 0 || batch[i - 1] != b) g_segs[b] = i;
        if (i == NATOMS - 1 || batch[i + 1] != b) g_sege[b] = i + 1;
        atomicAdd(&s_qp[b], qv);
    }
    __syncthreads();
    if (tid < NMOL && s_qp[tid] != 0.0f) atomicAdd(&g_qsumF[tid], s_qp[tid]);

    grid_barrier();

    // ---- qmean staging ------------------------------------------------------
    if (tid < NMOL) {
        const int cnt = g_sege[tid] - g_segs[tid];
        s_qmean[tid] = (cnt > 0) ? g_qsumF[tid] / (float)cnt : 0.0f;
    }
    __syncthreads();

    // ---- Pairwise energy (i<j; all terms symmetric), strided + pipelined ---
    double acc2 = 0.0;
    for (int i = bid * NWARP + w; i < NATOMS; i += NWTOT) {
        const int b  = batch[i];
        const int e0 = g_sege[b];
        const float qm = s_qmean[b];

        const float4 Ai = g_A[i];
        const float4 Bi = g_B[i];
        const float qi14 = (Ai.w - qm) * 14.399f;

        float facc = 0.0f;
        int j = i + 1 + lane;
        if (j < e0) {
            float4 Aj = g_A[j];
            float4 Bj = g_B[j];
            while (true) {
                const int jn = j + 32;
                float4 An, Bn;
                if (jn < e0) { An = g_A[jn]; Bn = g_B[jn]; }   // prefetch

                const float dx = Ai.x - Aj.x;
                const float dy = Ai.y - Aj.y;
                const float dz = Ai.z - Aj.z;
                const float d2r  = dx * dx + dy * dy + dz * dz;
                const float d2   = d2r + 1e-8f;
                const float invd = rsqrtf(d2);                    // MUFU 1
                const float dist = d2 * invd;

                const float qj    = Aj.w - qm;
                const float taper = 1.0f - __expf(-0.5f * dist);  // MUFU 2
                const float ec    = qi14 * qj * invd * taper;

                const float r6    = d2r * d2r * d2r;
                const float aden  = r6 + 20.0f;
                const float bden  = d2r * dist + 10.0f;
                const float invab = __fdividef(1.0f, aden * bden); // MUFU 3

                const float ev = -Bi.w * Bj.w * (invab * bden);

                const float mumu = Bi.x * Bj.x + Bi.y * Bj.y + Bi.z * Bj.z;
                const float di   = (Bi.x * dx + Bi.y * dy + Bi.z * dz) * invd;
                const float dj   = (Bj.x * dx + Bj.y * dy + Bj.z * dz) * invd;
                const float ed   = (mumu - 3.0f * di * dj) * (invab * aden);

                facc += ec + ev + ed;

                if (jn >= e0) break;
                Aj = An; Bj = Bn; j = jn;
            }
        }
        acc2 += (double)facc;
    }

    #pragma unroll
    for (int o = 16; o > 0; o >>= 1)
        acc2 += __shfl_down_sync(0xffffffffu, acc2, o);
    if (lane == 0) sDD[w] = acc2;
    __syncthreads();
    if (tid == 0) {
        double ts = 0.0;
        #pragma unroll
        for (int k = 0; k < NWARP; k++) ts += sDD[k];
        g_partial[bid] = ts;
        __threadfence();
        s_last = (atomicAdd(&g_done, 1) == NBLK - 1) ? 1 : 0;
    }
    __syncthreads();

    // ---- Last-arriving block: reset replay state, reduce, write output -----
    if (s_last) {
        __threadfence();
        if (tid == 0) g_done = 0;
        if (tid < NMOL) g_qsumF[tid] = 0.0f;   // all readers finished (ticket)
        double v = (tid < NBLK) ? g_partial[tid] : 0.0;
        #pragma unroll
        for (int o = 16; o > 0; o >>= 1)
            v += __shfl_down_sync(0xffffffffu, v, o);
        if (lane == 0 && w < 5) sDD[w] = v;
        __syncthreads();
        if (tid == 0) {
            double tot = 0.0;
            #pragma unroll
            for (int k = 0; k < 5; k++) tot += sDD[k];
            out[0] = (float)tot;               // LONG_RANGE_SCALE = 1.0
        }
    }
}

// ---------------------------------------------------------------------------
extern "C" void kernel_launch(void* const* d_in, const int* in_sizes, int n_in,
                              void* d_out, int out_size) {
    const float* h0    = (const float*)d_in[0];
    const float* h1    = (const float*)d_in[1];
    const float* pos   = (const float*)d_in[2];
    const int*   batch = (const int*)  d_in[3];
    const float* qW1   = (const float*)d_in[4];
    const float* qb1   = (const float*)d_in[5];
    const float* qW2   = (const float*)d_in[6];
    const float* qb2   = (const float*)d_in[7];
    const float* cW1   = (const float*)d_in[8];
    const float* cb1   = (const float*)d_in[9];
    const float* cW2   = (const float*)d_in[10];
    const float* cb2   = (const float*)d_in[11];
    const float* muW   = (const float*)d_in[12];

    const int smem_bytes = SMEM_WORDS * 4;     // 161280 B
    cudaFuncSetAttribute(fused_kernel,
                         cudaFuncAttributeMaxDynamicSharedMemorySize, smem_bytes);
    fused_kernel<<<NBLK, NTHR, smem_bytes>>>(
        h0, h1, pos, batch,
        qW1, qb1, qW2, qb2,
        cW1, cb1, cW2, cb2,
        muW, (float*)d_out);
}

// round 16
// speedup vs baseline: 1.0732x; 1.0168x over previous
#include <cuda_runtime.h>
#include <cstdint>

#define NATOMS 6144
#define FDIM   128
#define HDIM   64
#define NMOL   48
#define NBLK   148     // co-resident on B300(148)/GB300(152)
#define NTHR   768
#define NWARP  24
#define NWTOT  (NBLK * NWARP)
#define AROW   48      // padded atom rows (3 m-tiles of 16); acnt is 41..42
#define WPAD   68      // row stride in 32-bit words (136 bf16) -> conflict-free frags

// smem word offsets (uint32 units) — no fp32 weight buffer anymore
#define OFF_AH  0                  // A-hi bf16: 48*68 = 3264 words
#define OFF_AL  (OFF_AH + 3264)
#define OFF_WH  (OFF_AL + 3264)    // W-hi bf16: 128*68 = 8704 words
#define OFF_WL  (OFF_WH + 8704)
#define SMEM_WORDS (OFF_WL + 8704) // 23936 words = 93.5 KB

// Device-global scratch. Deterministic overwrites; g_qsumF zero at load and
// re-zeroed by the last-arriving block each replay (after all reads).
__device__ float4 g_A[NATOMS];        // pos.xyz, q_raw
__device__ float4 g_B[NATOMS];        // mu.xyz, sqrt(softplus(c6))
__device__ int    g_segs[NMOL];
__device__ int    g_sege[NMOL];
__device__ float  g_qsumF[NMOL];
__device__ double g_partial[NBLK];
__device__ volatile int g_sense;
__device__ int    g_count;
__device__ int    g_done;

__device__ __forceinline__ void grid_barrier() {
    __syncthreads();
    if (threadIdx.x == 0) {
        int s = g_sense;
        __threadfence();
        if (atomicAdd(&g_count, 1) == NBLK - 1) {
            g_count = 0;
            __threadfence();
            g_sense = s ^ 1;
        } else {
            while (g_sense == s) { }
        }
    }
    __syncthreads();
    __threadfence();
}

// pack {low=x, high=y} as bf16x2 (hi) and the bf16x2 of the residuals (lo)
__device__ __forceinline__ uint2 bf16split2(float x, float y) {
    uint32_t h, l;
    asm("cvt.rn.bf16x2.f32 %0, %1, %2;" : "=r"(h) : "f"(y), "f"(x));
    const float rx = x - __uint_as_float(h << 16);
    const float ry = y - __uint_as_float(h & 0xffff0000u);
    asm("cvt.rn.bf16x2.f32 %0, %1, %2;" : "=r"(l) : "f"(ry), "f"(rx));
    return make_uint2(h, l);
}

__device__ __forceinline__ void mma16816(float* d, const uint32_t* a,
                                         uint32_t b0, uint32_t b1) {
    asm volatile(
        "mma.sync.aligned.m16n8k16.row.col.f32.bf16.bf16.f32 "
        "{%0,%1,%2,%3}, {%4,%5,%6,%7}, {%8,%9}, {%0,%1,%2,%3};"
        : "+f"(d[0]), "+f"(d[1]), "+f"(d[2]), "+f"(d[3])
        : "r"(a[0]), "r"(a[1]), "r"(a[2]), "r"(a[3]), "r"(b0), "r"(b1));
}

extern "C" __global__ void __launch_bounds__(NTHR, 1) fused_kernel(
    const float* __restrict__ h0, const float* __restrict__ h1,
    const float* __restrict__ pos, const int* __restrict__ batch,
    const float* __restrict__ qW1, const float* __restrict__ qb1,
    const float* __restrict__ qW2, const float* __restrict__ qb2,
    const float* __restrict__ cW1, const float* __restrict__ cb1,
    const float* __restrict__ cW2, const float* __restrict__ cb2,
    const float* __restrict__ muW, float* __restrict__ out)
{
    extern __shared__ uint32_t sm[];
    uint32_t* sAh = sm + OFF_AH;
    uint32_t* sAl = sm + OFF_AL;
    uint32_t* sWh = sm + OFF_WH;
    uint32_t* sWl = sm + OFF_WL;

    __shared__ float  sQ[AROW], sC[AROW];      // per-atom MLP outputs (atomic acc)
    __shared__ float  s_b1[128], s_w2[128];
    __shared__ float  s_mu[AROW][3];
    __shared__ float  s_qp[NMOL];
    __shared__ float  s_qmean[NMOL];
    __shared__ double sDD[NWARP];
    __shared__ int    s_last;

    const int tid  = threadIdx.x;
    const int bid  = blockIdx.x;
    const int w    = tid >> 5;
    const int lane = tid & 31;

    const int astart = (bid * NATOMS) / NBLK;
    const int aend   = ((bid + 1) * NATOMS) / NBLK;
    const int acnt   = aend - astart;          // 41 or 42

    if (tid < NMOL) s_qp[tid] = 0.0f;
    if (tid < AROW) { sQ[tid] = 0.0f; sC[tid] = 0.0f; }
    __syncthreads();

    // ========== Warp-specialized phase 1 ====================================
    if (w < 12) {
        // ---- stage b1 / W2 (units 0-63 q, 64-127 c6) -----------------------
        if (tid < 64)       { s_b1[tid] = qb1[tid];      s_w2[tid] = qW2[tid]; }
        else if (tid < 128) { s_b1[tid] = cb1[tid - 64]; s_w2[tid] = cW2[tid - 64]; }

        // ---- acts: LDG.128 -> bf16 hi/lo split -> STS (rows padded to 48) --
        #pragma unroll
        for (int s = 0; s < 4; s++) {
            const int idx = tid + s * 384;     // < 1536 = 48 rows x 32 float4
            const int a  = idx >> 5;
            const int f0 = (idx & 31) * 4;
            float4 v = make_float4(0.f, 0.f, 0.f, 0.f);
            if (a < acnt)
                v = *reinterpret_cast<const float4*>(
                        h0 + (size_t)(astart + a) * FDIM + f0);
            const uint2 p01 = bf16split2(v.x, v.y);
            const uint2 p23 = bf16split2(v.z, v.w);
            const int base = a * WPAD + (f0 >> 1);
            sAh[base]     = p01.x; sAh[base + 1] = p23.x;
            sAl[base]     = p01.y; sAl[base + 1] = p23.y;
        }

        // ---- weights: global fp32 -> bf16 hi/lo, [unit n][k] padded layout -
        // One pipelined pass (no TMA, no intermediate smem buffer).
        {
            uint16_t* wh16 = (uint16_t*)sWh;
            uint16_t* wl16 = (uint16_t*)sWl;
            const float2* qw2p = (const float2*)qW1;
            const float2* cw2p = (const float2*)cW1;
            #pragma unroll 4
            for (int e = tid; e < 8192; e += 384) {
                const int m  = e >> 12;        // 0 = q, 1 = c6
                const int r  = e & 4095;
                const int f  = r >> 5;         // k index
                const int up = r & 31;         // unit pair
                const float2 wv = __ldg((m ? cw2p : qw2p) + f * 32 + up);
                const uint2 hl = bf16split2(wv.x, wv.y);
                const int n = m * 64 + 2 * up;
                wh16[n * 136 + f]       = (uint16_t)(hl.x & 0xffffu);
                wh16[(n + 1) * 136 + f] = (uint16_t)(hl.x >> 16);
                wl16[n * 136 + f]       = (uint16_t)(hl.y & 0xffffu);
                wl16[(n + 1) * 136 + f] = (uint16_t)(hl.y >> 16);
            }
        }
        asm volatile("bar.sync 1, 384;" ::: "memory");

        // ---- HMMA GEMM: 12 warps = 3 m-tiles x 4 n-quads -------------------
        // D = Ah*Bh + Ah*Bl + Al*Bh  (split-bf16, fp32 accum)
        const int m  = w >> 2;                 // m-tile (rows 16m..16m+15)
        const int nq = w & 3;                  // n-quad (cols nq*32..nq*32+31)
        const int g  = lane >> 2;              // fragment group row/col
        const int t  = lane & 3;

        float D[4][4];
        #pragma unroll
        for (int nb = 0; nb < 4; nb++)
            #pragma unroll
            for (int k = 0; k < 4; k++) D[nb][k] = 0.0f;

        const int ar0 = (16 * m + g) * WPAD;
        const int ar1 = (16 * m + g + 8) * WPAD;

        #pragma unroll
        for (int kk = 0; kk < 8; kk++) {
            const int kw = kk * 8 + t;
            uint32_t ah[4], al[4];
            ah[0] = sAh[ar0 + kw];     ah[1] = sAh[ar1 + kw];
            ah[2] = sAh[ar0 + kw + 4]; ah[3] = sAh[ar1 + kw + 4];
            al[0] = sAl[ar0 + kw];     al[1] = sAl[ar1 + kw];
            al[2] = sAl[ar0 + kw + 4]; al[3] = sAl[ar1 + kw + 4];
            #pragma unroll
            for (int nb = 0; nb < 4; nb++) {
                const int wb = (nq * 32 + nb * 8 + g) * WPAD + kw;
                const uint32_t bh0 = sWh[wb], bh1 = sWh[wb + 4];
                const uint32_t bl0 = sWl[wb], bl1 = sWl[wb + 4];
                mma16816(D[nb], ah, bh0, bh1);
                mma16816(D[nb], ah, bl0, bl1);
                mma16816(D[nb], al, bh0, bh1);
            }
        }

        // ---- epilogue: silu * W2 in fragments, butterfly, shared atomics ---
        float sum0 = 0.0f, sum1 = 0.0f;
        #pragma unroll
        for (int nb = 0; nb < 4; nb++) {
            const int c0 = nq * 32 + nb * 8 + 2 * t;
            const int c1 = c0 + 1;
            const float b0 = s_b1[c0], b1v = s_b1[c1];
            const float w0 = s_w2[c0], w1v = s_w2[c1];
            float x;
            x = D[nb][0] + b0;  sum0 += x * __fdividef(1.0f, 1.0f + __expf(-x)) * w0;
            x = D[nb][1] + b1v; sum0 += x * __fdividef(1.0f, 1.0f + __expf(-x)) * w1v;
            x = D[nb][2] + b0;  sum1 += x * __fdividef(1.0f, 1.0f + __expf(-x)) * w0;
            x = D[nb][3] + b1v; sum1 += x * __fdividef(1.0f, 1.0f + __expf(-x)) * w1v;
        }
        sum0 += __shfl_xor_sync(0xffffffffu, sum0, 1);
        sum0 += __shfl_xor_sync(0xffffffffu, sum0, 2);
        sum1 += __shfl_xor_sync(0xffffffffu, sum1, 1);
        sum1 += __shfl_xor_sync(0xffffffffu, sum1, 2);
        if (t == 0) {
            float* dst = (nq < 2) ? sQ : sC;
            atomicAdd(&dst[16 * m + g],     sum0);
            atomicAdd(&dst[16 * m + g + 8], sum1);
        }
    } else {
        // ---- mu warps (12-23): 2-atom ILP, 2 serial DRAM rounds ------------
        const float4 mw4 = *reinterpret_cast<const float4*>(muW + lane * 4);
        for (int base = w - 12; base < acnt; base += 24) {
            const int loc1 = base + 12;
            const bool has2 = (loc1 < acnt);
            const float* hr0 = h1 + (size_t)(astart + base) * 3 * FDIM;
            const float* hr1 = h1 + (size_t)(astart + (has2 ? loc1 : base)) * 3 * FDIM;
            float m0[3], m1[3];
            #pragma unroll
            for (int d = 0; d < 3; d++) {
                const float4 a = *reinterpret_cast<const float4*>(hr0 + d * FDIM + lane * 4);
                const float4 b = *reinterpret_cast<const float4*>(hr1 + d * FDIM + lane * 4);
                m0[d] = a.x * mw4.x + a.y * mw4.y + a.z * mw4.z + a.w * mw4.w;
                m1[d] = b.x * mw4.x + b.y * mw4.y + b.z * mw4.z + b.w * mw4.w;
            }
            #pragma unroll
            for (int o = 16; o > 0; o >>= 1) {
                #pragma unroll
                for (int d = 0; d < 3; d++) {
                    m0[d] += __shfl_down_sync(0xffffffffu, m0[d], o);
                    m1[d] += __shfl_down_sync(0xffffffffu, m1[d], o);
                }
            }
            if (lane == 0) {
                s_mu[base][0] = m0[0]; s_mu[base][1] = m0[1]; s_mu[base][2] = m0[2];
                if (has2) { s_mu[loc1][0] = m1[0]; s_mu[loc1][1] = m1[1]; s_mu[loc1][2] = m1[2]; }
            }
        }
    }
    __syncthreads();

    // ---- Pack per-atom data + segment boundaries + molecule q partials -----
    if (tid < acnt) {
        const float qv = sQ[tid] + qb2[0];
        const float cv = sC[tid] + cb2[0];
        const float sp = fmaxf(cv, 0.0f) + log1pf(__expf(-fabsf(cv)));
        const int i = astart + tid;
        const int b = batch[i];
        g_A[i] = make_float4(pos[3 * i], pos[3 * i + 1], pos[3 * i + 2], qv);
        g_B[i] = make_float4(s_mu[tid][0], s_mu[tid][1], s_mu[tid][2], sqrtf(sp));
        if (i == 0 || batch[i - 1] != b) g_segs[b] = i;
        if (i == NATOMS - 1 || batch[i + 1] != b) g_sege[b] = i + 1;
        atomicAdd(&s_qp[b], qv);
    }
    __syncthreads();
    if (tid < NMOL && s_qp[tid] != 0.0f) atomicAdd(&g_qsumF[tid], s_qp[tid]);

    grid_barrier();

    // ---- qmean staging ------------------------------------------------------
    if (tid < NMOL) {
        const int cnt = g_sege[tid] - g_segs[tid];
        s_qmean[tid] = (cnt > 0) ? g_qsumF[tid] / (float)cnt : 0.0f;
    }
    __syncthreads();

    // ---- Pairwise energy (i<j; all terms symmetric), strided + pipelined ---
    double acc2 = 0.0;
    for (int i = bid * NWARP + w; i < NATOMS; i += NWTOT) {
        const int b  = batch[i];
        const int e0 = g_sege[b];
        const float qm = s_qmean[b];

        const float4 Ai = g_A[i];
        const float4 Bi = g_B[i];
        const float qi14 = (Ai.w - qm) * 14.399f;

        float facc = 0.0f;
        int j = i + 1 + lane;
        if (j < e0) {
            float4 Aj = g_A[j];
            float4 Bj = g_B[j];
            while (true) {
                const int jn = j + 32;
                float4 An, Bn;
                if (jn < e0) { An = g_A[jn]; Bn = g_B[jn]; }   // prefetch

                const float dx = Ai.x - Aj.x;
                const float dy = Ai.y - Aj.y;
                const float dz = Ai.z - Aj.z;
                const float d2r  = dx * dx + dy * dy + dz * dz;
                const float d2   = d2r + 1e-8f;
                const float invd = rsqrtf(d2);                    // MUFU 1
                const float dist = d2 * invd;

                const float qj    = Aj.w - qm;
                const float taper = 1.0f - __expf(-0.5f * dist);  // MUFU 2
                const float ec    = qi14 * qj * invd * taper;

                const float r6    = d2r * d2r * d2r;
                const float aden  = r6 + 20.0f;
                const float bden  = d2r * dist + 10.0f;
                const float invab = __fdividef(1.0f, aden * bden); // MUFU 3

                const float ev = -Bi.w * Bj.w * (invab * bden);

                const float mumu = Bi.x * Bj.x + Bi.y * Bj.y + Bi.z * Bj.z;
                const float di   = (Bi.x * dx + Bi.y * dy + Bi.z * dz) * invd;
                const float dj   = (Bj.x * dx + Bj.y * dy + Bj.z * dz) * invd;
                const float ed   = (mumu - 3.0f * di * dj) * (invab * aden);

                facc += ec + ev + ed;

                if (jn >= e0) break;
                Aj = An; Bj = Bn; j = jn;
            }
        }
        acc2 += (double)facc;
    }

    #pragma unroll
    for (int o = 16; o > 0; o >>= 1)
        acc2 += __shfl_down_sync(0xffffffffu, acc2, o);
    if (lane == 0) sDD[w] = acc2;
    __syncthreads();
    if (tid == 0) {
        double ts = 0.0;
        #pragma unroll
        for (int k = 0; k < NWARP; k++) ts += sDD[k];
        g_partial[bid] = ts;
        __threadfence();
        s_last = (atomicAdd(&g_done, 1) == NBLK - 1) ? 1 : 0;
    }
    __syncthreads();

    // ---- Last-arriving block: reset replay state, reduce, write output -----
    if (s_last) {
        __threadfence();
        if (tid == 0) g_done = 0;
        if (tid < NMOL) g_qsumF[tid] = 0.0f;   // all readers finished (ticket)
        double v = (tid < NBLK) ? g_partial[tid] : 0.0;
        #pragma unroll
        for (int o = 16; o > 0; o >>= 1)
            v += __shfl_down_sync(0xffffffffu, v, o);
        if (lane == 0 && w < 5) sDD[w] = v;
        __syncthreads();
        if (tid == 0) {
            double tot = 0.0;
            #pragma unroll
            for (int k = 0; k < 5; k++) tot += sDD[k];
            out[0] = (float)tot;               // LONG_RANGE_SCALE = 1.0
        }
    }
}

// ---------------------------------------------------------------------------
extern "C" void kernel_launch(void* const* d_in, const int* in_sizes, int n_in,
                              void* d_out, int out_size) {
    const float* h0    = (const float*)d_in[0];
    const float* h1    = (const float*)d_in[1];
    const float* pos   = (const float*)d_in[2];
    const int*   batch = (const int*)  d_in[3];
    const float* qW1   = (const float*)d_in[4];
    const float* qb1   = (const float*)d_in[5];
    const float* qW2   = (const float*)d_in[6];
    const float* qb2   = (const float*)d_in[7];
    const float* cW1   = (const float*)d_in[8];
    const float* cb1   = (const float*)d_in[9];
    const float* cW2   = (const float*)d_in[10];
    const float* cb2   = (const float*)d_in[11];
    const float* muW   = (const float*)d_in[12];

    const int smem_bytes = SMEM_WORDS * 4;     // 95744 B
    cudaFuncSetAttribute(fused_kernel,
                         cudaFuncAttributeMaxDynamicSharedMemorySize, smem_bytes);
    fused_kernel<<<NBLK, NTHR, smem_bytes>>>(
        h0, h1, pos, batch,
        qW1, qb1, qW2, qb2,
        cW1, cb1, cW2, cb2,
        muW, (float*)d_out);
}